// round 2
// baseline (speedup 1.0000x reference)
#include <cuda_runtime.h>
#include <cuda_bf16.h>

// EGNN layer, B=2, N=16384, K=16, H=128.
// One CTA (128 threads) per node. Thread t owns output channel t.
// The 16 edges are processed as 8 packed f32x2 pairs (k, k+8) so the three
// dominant 128x128(x16-edge) matvec stages run on packed fma.rn.f32x2
// (FFMA2), halving FMA-pipe issue vs scalar FFMA. Features are staged in
// shared memory PRE-PACKED as float2 so packing cost is paid once.
// The h_i contribution to edge-MLP layer 1 is k-invariant and hoisted.

#define HDIM 128
#define BATCH 2
#define NPTS 16384
#define KNBR 16
#define NPAIR 8
#define STR2 130   // float2 stride per pair row-block (even => 16B-aligned rows)

typedef unsigned long long u64v;

__device__ __forceinline__ float silu_f(float v) {
    return v / (1.0f + __expf(-v));
}

__device__ __forceinline__ u64v pk2(float lo, float hi) {
    u64v r;
    asm("mov.b64 %0, {%1, %2};" : "=l"(r) : "f"(lo), "f"(hi));
    return r;
}
__device__ __forceinline__ void upk2(float& lo, float& hi, u64v v) {
    asm("mov.b64 {%0, %1}, %2;" : "=f"(lo), "=f"(hi) : "l"(v));
}
__device__ __forceinline__ u64v fma2(u64v a, u64v b, u64v c) {
    u64v d;
    asm("fma.rn.f32x2 %0, %1, %2, %3;" : "=l"(d) : "l"(a), "l"(b), "l"(c));
    return d;
}
__device__ __forceinline__ u64v silu2(u64v v) {
    float lo, hi;
    upk2(lo, hi, v);
    return pk2(silu_f(lo), silu_f(hi));
}

__global__ void __launch_bounds__(128)
egnn_layer_kernel(const float* __restrict__ h, const float* __restrict__ x,
                  const int* __restrict__ eidx,
                  const float* __restrict__ We1, const float* __restrict__ be1,
                  const float* __restrict__ We2, const float* __restrict__ be2,
                  const float* __restrict__ Wc1, const float* __restrict__ bc1,
                  const float* __restrict__ Wc2,
                  const float* __restrict__ Wn1, const float* __restrict__ bn1,
                  const float* __restrict__ Wn2, const float* __restrict__ bn2,
                  float* __restrict__ hout, float* __restrict__ xout)
{
    __shared__ __align__(16) float2 bufAp[NPAIR * STR2]; // packed h_j, later packed m_ij
    __shared__ __align__(16) float2 bufBp[NPAIR * STR2]; // packed e1, later plain c1 rows
    __shared__ __align__(16) float shi[HDIM];            // h_i
    __shared__ __align__(16) float msum[HDIM];           // sum_k m_ij
    __shared__ __align__(16) float n1b[HDIM];            // node mlp hidden
    __shared__ float sq[KNBR];
    __shared__ float xdf[KNBR][3];
    __shared__ float cw[KNBR];
    __shared__ int   sidx[KNBR];
    __shared__ float sxi[3];

    const int t   = threadIdx.x;
    const int bid = blockIdx.x;           // = b*NPTS + n
    const int b   = bid / NPTS;

    // ---- stage 0: load node data + indices ----
    shi[t] = h[(long)bid * HDIM + t];
    if (t < KNBR) sidx[t] = eidx[(long)bid * KNBR + t];
    if (t < 3)    sxi[t]  = x[(long)bid * 3 + t];
    __syncthreads();

    // per-edge coordinate terms (threads 0..15)
    if (t < KNBR) {
        int j = sidx[t];
        const float* xj = x + ((long)b * NPTS + j) * 3;
        float dx = sxi[0] - xj[0];
        float dy = sxi[1] - xj[1];
        float dz = sxi[2] - xj[2];
        xdf[t][0] = dx; xdf[t][1] = dy; xdf[t][2] = dz;
        sq[t] = dx*dx + dy*dy + dz*dz;
    }

    // gather h_j rows PRE-PACKED: pair p holds {h_{j(p)}[d], h_{j(p+8)}[d]}.
    // Warp w handles pairs p = w and w+4.
    {
        int w = t >> 5, l = t & 31;
        #pragma unroll
        for (int pp = 0; pp < 2; pp++) {
            int p  = w + 4 * pp;
            const float4* A = (const float4*)(h + ((long)b * NPTS + sidx[p]) * HDIM);
            const float4* Bq = (const float4*)(h + ((long)b * NPTS + sidx[p + 8]) * HDIM);
            float4 a = A[l];
            float4 c = Bq[l];
            float2* dst = &bufAp[p * STR2 + 4 * l];
            dst[0] = make_float2(a.x, c.x);
            dst[1] = make_float2(a.y, c.y);
            dst[2] = make_float2(a.z, c.z);
            dst[3] = make_float2(a.w, c.w);
        }
    }
    __syncthreads();

    u64v acc2[NPAIR];

    // ---- edge MLP layer 1: e1 = silu([h_i, h_j, sq] @ We1 + be1) ----
    {
        // k-invariant h_i part (scalar)
        float a0 = be1[t];
        #pragma unroll 4
        for (int d = 0; d < HDIM; d += 4) {
            float4 f = *(const float4*)&shi[d];
            a0 = fmaf(f.x, We1[(d + 0) * HDIM + t], a0);
            a0 = fmaf(f.y, We1[(d + 1) * HDIM + t], a0);
            a0 = fmaf(f.z, We1[(d + 2) * HDIM + t], a0);
            a0 = fmaf(f.w, We1[(d + 3) * HDIM + t], a0);
        }
        u64v a02 = pk2(a0, a0);
        #pragma unroll
        for (int p = 0; p < NPAIR; p++) acc2[p] = a02;

        const float* W1b = We1 + HDIM * HDIM;  // rows 128..255 (h_j part)
        for (int d = 0; d < HDIM; d += 4) {
            u64v w0 = pk2(W1b[(d + 0) * HDIM + t], W1b[(d + 0) * HDIM + t]);
            u64v w1 = pk2(W1b[(d + 1) * HDIM + t], W1b[(d + 1) * HDIM + t]);
            u64v w2 = pk2(W1b[(d + 2) * HDIM + t], W1b[(d + 2) * HDIM + t]);
            u64v w3 = pk2(W1b[(d + 3) * HDIM + t], W1b[(d + 3) * HDIM + t]);
            #pragma unroll
            for (int p = 0; p < NPAIR; p++) {
                const ulonglong2* fp = (const ulonglong2*)&bufAp[p * STR2 + d];
                ulonglong2 q0 = fp[0];   // rows d, d+1
                ulonglong2 q1 = fp[1];   // rows d+2, d+3
                acc2[p] = fma2(q0.x, w0, acc2[p]);
                acc2[p] = fma2(q0.y, w1, acc2[p]);
                acc2[p] = fma2(q1.x, w2, acc2[p]);
                acc2[p] = fma2(q1.y, w3, acc2[p]);
            }
        }
        float wq = We1[(2 * HDIM) * HDIM + t];  // row 256 (sq_dist)
        u64v wq2 = pk2(wq, wq);
        #pragma unroll
        for (int p = 0; p < NPAIR; p++) {
            acc2[p] = fma2(pk2(sq[p], sq[p + 8]), wq2, acc2[p]);
            acc2[p] = silu2(acc2[p]);
            *(u64v*)&bufBp[p * STR2 + t] = acc2[p];   // packed e1
        }
    }
    __syncthreads();

    // ---- edge MLP layer 2: m_ij = silu(e1 @ We2 + be2) ----
    {
        float b2 = be2[t];
        u64v b22 = pk2(b2, b2);
        #pragma unroll
        for (int p = 0; p < NPAIR; p++) acc2[p] = b22;
        for (int d = 0; d < HDIM; d += 4) {
            u64v w0 = pk2(We2[(d + 0) * HDIM + t], We2[(d + 0) * HDIM + t]);
            u64v w1 = pk2(We2[(d + 1) * HDIM + t], We2[(d + 1) * HDIM + t]);
            u64v w2 = pk2(We2[(d + 2) * HDIM + t], We2[(d + 2) * HDIM + t]);
            u64v w3 = pk2(We2[(d + 3) * HDIM + t], We2[(d + 3) * HDIM + t]);
            #pragma unroll
            for (int p = 0; p < NPAIR; p++) {
                const ulonglong2* fp = (const ulonglong2*)&bufBp[p * STR2 + d];
                ulonglong2 q0 = fp[0];
                ulonglong2 q1 = fp[1];
                acc2[p] = fma2(q0.x, w0, acc2[p]);
                acc2[p] = fma2(q0.y, w1, acc2[p]);
                acc2[p] = fma2(q1.x, w2, acc2[p]);
                acc2[p] = fma2(q1.y, w3, acc2[p]);
            }
        }
        #pragma unroll
        for (int p = 0; p < NPAIR; p++) acc2[p] = silu2(acc2[p]);
    }
    __syncthreads();   // all bufAp (gather) reads done
    {
        float s = 0.0f;
        #pragma unroll
        for (int p = 0; p < NPAIR; p++) {
            *(u64v*)&bufAp[p * STR2 + t] = acc2[p];   // packed m_ij
            float lo, hi;
            upk2(lo, hi, acc2[p]);
            s += lo + hi;
        }
        msum[t] = s;                                  // m_i
    }
    __syncthreads();

    // ---- coord MLP layer 1: c1 = silu(m_ij @ Wc1 + bc1) -> plain rows ----
    {
        float b1 = bc1[t];
        u64v b12 = pk2(b1, b1);
        #pragma unroll
        for (int p = 0; p < NPAIR; p++) acc2[p] = b12;
        for (int d = 0; d < HDIM; d += 4) {
            u64v w0 = pk2(Wc1[(d + 0) * HDIM + t], Wc1[(d + 0) * HDIM + t]);
            u64v w1 = pk2(Wc1[(d + 1) * HDIM + t], Wc1[(d + 1) * HDIM + t]);
            u64v w2 = pk2(Wc1[(d + 2) * HDIM + t], Wc1[(d + 2) * HDIM + t]);
            u64v w3 = pk2(Wc1[(d + 3) * HDIM + t], Wc1[(d + 3) * HDIM + t]);
            #pragma unroll
            for (int p = 0; p < NPAIR; p++) {
                const ulonglong2* fp = (const ulonglong2*)&bufAp[p * STR2 + d];
                ulonglong2 q0 = fp[0];
                ulonglong2 q1 = fp[1];
                acc2[p] = fma2(q0.x, w0, acc2[p]);
                acc2[p] = fma2(q0.y, w1, acc2[p]);
                acc2[p] = fma2(q1.x, w2, acc2[p]);
                acc2[p] = fma2(q1.y, w3, acc2[p]);
            }
        }
    }
    __syncthreads();   // bufBp (e1) reads done; reuse as plain float c1 rows
    {
        float* bufBf = (float*)bufBp;                 // 16 rows, stride 130 floats
        #pragma unroll
        for (int p = 0; p < NPAIR; p++) {
            float lo, hi;
            upk2(lo, hi, acc2[p]);
            bufBf[p * STR2 + t]       = silu_f(lo);   // edge p
            bufBf[(p + 8) * STR2 + t] = silu_f(hi);   // edge p+8
        }
    }
    __syncthreads();

    // ---- coord_w[k] = c1[k] . Wc2  (warp w reduces k = 4w..4w+3) ----
    {
        const float* bufBf = (const float*)bufBp;
        int w = t >> 5, l = t & 31;
        float c0 = Wc2[l], c1v = Wc2[l + 32], c2 = Wc2[l + 64], c3 = Wc2[l + 96];
        #pragma unroll
        for (int kk = 0; kk < 4; kk++) {
            int k = w * 4 + kk;
            const float* row = &bufBf[k * STR2];
            float p = row[l] * c0 + row[l + 32] * c1v + row[l + 64] * c2 + row[l + 96] * c3;
            p += __shfl_xor_sync(0xffffffffu, p, 16);
            p += __shfl_xor_sync(0xffffffffu, p, 8);
            p += __shfl_xor_sync(0xffffffffu, p, 4);
            p += __shfl_xor_sync(0xffffffffu, p, 2);
            p += __shfl_xor_sync(0xffffffffu, p, 1);
            if (l == 0) cw[k] = p;
        }
    }
    __syncthreads();

    // ---- x_new (threads 0..2, one component each) ----
    if (t < 3) {
        float s = 0.0f;
        #pragma unroll
        for (int k = 0; k < KNBR; k++) s += xdf[k][t] * cw[k];
        xout[(long)bid * 3 + t] = sxi[t] + s * (1.0f / (float)KNBR);
    }

    // ---- node MLP: h_new = silu([h_i, m_i] @ Wn1 + bn1) @ Wn2 + bn2 + h_i ----
    {
        float na = bn1[t];
        #pragma unroll 4
        for (int d = 0; d < HDIM; d += 4) {
            float4 f = *(const float4*)&shi[d];
            na = fmaf(f.x, Wn1[(d + 0) * HDIM + t], na);
            na = fmaf(f.y, Wn1[(d + 1) * HDIM + t], na);
            na = fmaf(f.z, Wn1[(d + 2) * HDIM + t], na);
            na = fmaf(f.w, Wn1[(d + 3) * HDIM + t], na);
        }
        const float* Wn1b = Wn1 + HDIM * HDIM;
        #pragma unroll 4
        for (int d = 0; d < HDIM; d += 4) {
            float4 f = *(const float4*)&msum[d];
            na = fmaf(f.x, Wn1b[(d + 0) * HDIM + t], na);
            na = fmaf(f.y, Wn1b[(d + 1) * HDIM + t], na);
            na = fmaf(f.z, Wn1b[(d + 2) * HDIM + t], na);
            na = fmaf(f.w, Wn1b[(d + 3) * HDIM + t], na);
        }
        n1b[t] = silu_f(na);
    }
    __syncthreads();
    {
        float oa = bn2[t] + shi[t];
        #pragma unroll 4
        for (int d = 0; d < HDIM; d += 4) {
            float4 f = *(const float4*)&n1b[d];
            oa = fmaf(f.x, Wn2[(d + 0) * HDIM + t], oa);
            oa = fmaf(f.y, Wn2[(d + 1) * HDIM + t], oa);
            oa = fmaf(f.z, Wn2[(d + 2) * HDIM + t], oa);
            oa = fmaf(f.w, Wn2[(d + 3) * HDIM + t], oa);
        }
        hout[(long)bid * HDIM + t] = oa;
    }
}

extern "C" void kernel_launch(void* const* d_in, const int* in_sizes, int n_in,
                              void* d_out, int out_size) {
    const float* h    = (const float*)d_in[0];
    const float* x    = (const float*)d_in[1];
    const int*   eidx = (const int*)d_in[2];
    const float* We1  = (const float*)d_in[3];
    const float* be1  = (const float*)d_in[4];
    const float* We2  = (const float*)d_in[5];
    const float* be2  = (const float*)d_in[6];
    const float* Wc1  = (const float*)d_in[7];
    const float* bc1  = (const float*)d_in[8];
    const float* Wc2  = (const float*)d_in[9];
    const float* Wn1  = (const float*)d_in[10];
    const float* bn1  = (const float*)d_in[11];
    const float* Wn2  = (const float*)d_in[12];
    const float* bn2  = (const float*)d_in[13];

    float* hout = (float*)d_out;                                  // (B,N,H)
    float* xout = (float*)d_out + (long)BATCH * NPTS * HDIM;      // (B,N,3)

    dim3 grid(BATCH * NPTS);
    dim3 block(128);
    egnn_layer_kernel<<<grid, block>>>(h, x, eidx,
                                       We1, be1, We2, be2,
                                       Wc1, bc1, Wc2,
                                       Wn1, bn1, Wn2, bn2,
                                       hout, xout);
}

// round 4
// speedup vs baseline: 1.0244x; 1.0244x over previous
#include <cuda_runtime.h>
#include <cuda_bf16.h>

// EGNN layer, B=2, N=16384, K=16, H=128.
// One CTA (128 threads) per TWO nodes. Thread t owns output channel t.
// 2 nodes x 16 edges = 32 edges are processed as 16 packed f32x2 pairs
// (edge k, edge k+8 of the same node) so the three dominant matvec stages run
// on packed fma.rn.f32x2 AND each weight load is amortized over 32 edges
// (vs 16 before), halving the dominant L1 weight-reread traffic.
// Node-MLP and the k-invariant h_i pass also share weight loads across the
// two nodes.

#define HDIM 128
#define BATCH 2
#define NPTS 16384
#define KNBR 16
#define NODES 2
#define NPAIR 8
#define NPG (NODES * NPAIR)   // 16 pair-groups: q = g*8 + p
#define STR2 130              // float2 stride per pair row-block (even => 16B rows)

typedef unsigned long long u64v;

__device__ __forceinline__ float silu_f(float v) {
    return v / (1.0f + __expf(-v));
}

__device__ __forceinline__ u64v pk2(float lo, float hi) {
    u64v r;
    asm("mov.b64 %0, {%1, %2};" : "=l"(r) : "f"(lo), "f"(hi));
    return r;
}
__device__ __forceinline__ void upk2(float& lo, float& hi, u64v v) {
    asm("mov.b64 {%0, %1}, %2;" : "=f"(lo), "=f"(hi) : "l"(v));
}
__device__ __forceinline__ u64v fma2(u64v a, u64v b, u64v c) {
    u64v d;
    asm("fma.rn.f32x2 %0, %1, %2, %3;" : "=l"(d) : "l"(a), "l"(b), "l"(c));
    return d;
}
__device__ __forceinline__ u64v silu2(u64v v) {
    float lo, hi;
    upk2(lo, hi, v);
    return pk2(silu_f(lo), silu_f(hi));
}

__global__ void __launch_bounds__(128)
egnn_layer_kernel(const float* __restrict__ h, const float* __restrict__ x,
                  const int* __restrict__ eidx,
                  const float* __restrict__ We1, const float* __restrict__ be1,
                  const float* __restrict__ We2, const float* __restrict__ be2,
                  const float* __restrict__ Wc1, const float* __restrict__ bc1,
                  const float* __restrict__ Wc2,
                  const float* __restrict__ Wn1, const float* __restrict__ bn1,
                  const float* __restrict__ Wn2, const float* __restrict__ bn2,
                  float* __restrict__ hout, float* __restrict__ xout)
{
    __shared__ __align__(16) float2 bufAp[NPG * STR2]; // packed h_j, later packed m_ij
    __shared__ __align__(16) float2 bufBp[NPG * STR2]; // packed e1, later plain c1 rows
    __shared__ __align__(16) float shi[NODES][HDIM];   // h_i
    __shared__ __align__(16) float msum[NODES][HDIM];  // sum_k m_ij
    __shared__ __align__(16) float n1b[NODES][HDIM];   // node mlp hidden
    __shared__ float sq[NODES][KNBR];
    __shared__ float xdf[NODES][KNBR][3];
    __shared__ float cw[NODES][KNBR];
    __shared__ int   sidx[NODES][KNBR];
    __shared__ float sxi[NODES][3];

    const int t  = threadIdx.x;
    const int n0 = blockIdx.x * NODES;    // first global node id (= b*NPTS + n)
    const int b  = n0 / NPTS;             // NPTS even => both nodes same batch

    // ---- stage 0: load node data + indices ----
    shi[0][t] = h[(long)n0 * HDIM + t];
    shi[1][t] = h[(long)(n0 + 1) * HDIM + t];
    if (t < NODES * KNBR) {
        int g = t >> 4, k = t & 15;
        sidx[g][k] = eidx[(long)(n0 + g) * KNBR + k];
    }
    if (t < NODES * 3) {
        int g = t / 3, c = t % 3;
        sxi[g][c] = x[(long)(n0 + g) * 3 + c];
    }
    __syncthreads();

    // per-edge coordinate terms
    if (t < NODES * KNBR) {
        int g = t >> 4, k = t & 15;
        int j = sidx[g][k];
        const float* xj = x + ((long)b * NPTS + j) * 3;
        float dx = sxi[g][0] - xj[0];
        float dy = sxi[g][1] - xj[1];
        float dz = sxi[g][2] - xj[2];
        xdf[g][k][0] = dx; xdf[g][k][1] = dy; xdf[g][k][2] = dz;
        sq[g][k] = dx*dx + dy*dy + dz*dz;
    }

    // gather h_j rows PRE-PACKED: group q=g*8+p holds {h_j(k=p), h_j(k=p+8)} of node g.
    // Warp w handles p = w and w+4 for both nodes.
    {
        int w = t >> 5, l = t & 31;
        #pragma unroll
        for (int g = 0; g < NODES; g++) {
            #pragma unroll
            for (int pp = 0; pp < 2; pp++) {
                int p = w + 4 * pp;
                const float4* A  = (const float4*)(h + ((long)b * NPTS + sidx[g][p]) * HDIM);
                const float4* Bq = (const float4*)(h + ((long)b * NPTS + sidx[g][p + 8]) * HDIM);
                float4 a = A[l];
                float4 c = Bq[l];
                float2* dst = &bufAp[(g * NPAIR + p) * STR2 + 4 * l];
                dst[0] = make_float2(a.x, c.x);
                dst[1] = make_float2(a.y, c.y);
                dst[2] = make_float2(a.z, c.z);
                dst[3] = make_float2(a.w, c.w);
            }
        }
    }
    __syncthreads();

    u64v acc2[NPG];

    // ---- edge MLP layer 1: e1 = silu([h_i, h_j, sq] @ We1 + be1) ----
    {
        // k-invariant h_i part (both nodes share weight loads)
        float a00 = be1[t], a01 = be1[t];
        #pragma unroll 4
        for (int d = 0; d < HDIM; d += 4) {
            float w0 = We1[(d + 0) * HDIM + t];
            float w1 = We1[(d + 1) * HDIM + t];
            float w2 = We1[(d + 2) * HDIM + t];
            float w3 = We1[(d + 3) * HDIM + t];
            float4 f0 = *(const float4*)&shi[0][d];
            float4 f1 = *(const float4*)&shi[1][d];
            a00 = fmaf(f0.x, w0, a00); a01 = fmaf(f1.x, w0, a01);
            a00 = fmaf(f0.y, w1, a00); a01 = fmaf(f1.y, w1, a01);
            a00 = fmaf(f0.z, w2, a00); a01 = fmaf(f1.z, w2, a01);
            a00 = fmaf(f0.w, w3, a00); a01 = fmaf(f1.w, w3, a01);
        }
        u64v i0 = pk2(a00, a00), i1 = pk2(a01, a01);
        #pragma unroll
        for (int q = 0; q < NPG; q++) acc2[q] = (q < NPAIR) ? i0 : i1;

        const float* W1b = We1 + HDIM * HDIM;  // rows 128..255 (h_j part)
        for (int d = 0; d < HDIM; d += 4) {
            float s0 = W1b[(d + 0) * HDIM + t];
            float s1 = W1b[(d + 1) * HDIM + t];
            float s2 = W1b[(d + 2) * HDIM + t];
            float s3 = W1b[(d + 3) * HDIM + t];
            u64v w0 = pk2(s0, s0), w1 = pk2(s1, s1), w2 = pk2(s2, s2), w3 = pk2(s3, s3);
            #pragma unroll
            for (int q = 0; q < NPG; q++) {
                const ulonglong2* fp = (const ulonglong2*)&bufAp[q * STR2 + d];
                ulonglong2 q0 = fp[0];   // rows d, d+1
                ulonglong2 q1 = fp[1];   // rows d+2, d+3
                acc2[q] = fma2(q0.x, w0, acc2[q]);
                acc2[q] = fma2(q0.y, w1, acc2[q]);
                acc2[q] = fma2(q1.x, w2, acc2[q]);
                acc2[q] = fma2(q1.y, w3, acc2[q]);
            }
        }
        float wq = We1[(2 * HDIM) * HDIM + t];  // row 256 (sq_dist)
        u64v wq2 = pk2(wq, wq);
        #pragma unroll
        for (int q = 0; q < NPG; q++) {
            int g = q >> 3, p = q & 7;
            acc2[q] = fma2(pk2(sq[g][p], sq[g][p + 8]), wq2, acc2[q]);
            acc2[q] = silu2(acc2[q]);
            *(u64v*)&bufBp[q * STR2 + t] = acc2[q];   // packed e1
        }
    }
    __syncthreads();

    // ---- edge MLP layer 2: m_ij = silu(e1 @ We2 + be2) ----
    {
        float b2 = be2[t];
        u64v b22 = pk2(b2, b2);
        #pragma unroll
        for (int q = 0; q < NPG; q++) acc2[q] = b22;
        for (int d = 0; d < HDIM; d += 4) {
            float s0 = We2[(d + 0) * HDIM + t];
            float s1 = We2[(d + 1) * HDIM + t];
            float s2 = We2[(d + 2) * HDIM + t];
            float s3 = We2[(d + 3) * HDIM + t];
            u64v w0 = pk2(s0, s0), w1 = pk2(s1, s1), w2 = pk2(s2, s2), w3 = pk2(s3, s3);
            #pragma unroll
            for (int q = 0; q < NPG; q++) {
                const ulonglong2* fp = (const ulonglong2*)&bufBp[q * STR2 + d];
                ulonglong2 q0 = fp[0];
                ulonglong2 q1 = fp[1];
                acc2[q] = fma2(q0.x, w0, acc2[q]);
                acc2[q] = fma2(q0.y, w1, acc2[q]);
                acc2[q] = fma2(q1.x, w2, acc2[q]);
                acc2[q] = fma2(q1.y, w3, acc2[q]);
            }
        }
        // silu, store packed m_ij (bufAp gather no longer needed), accumulate m_i
        float s0 = 0.0f, s1 = 0.0f;
        #pragma unroll
        for (int q = 0; q < NPG; q++) {
            acc2[q] = silu2(acc2[q]);
            *(u64v*)&bufAp[q * STR2 + t] = acc2[q];
            float lo, hi;
            upk2(lo, hi, acc2[q]);
            if (q < NPAIR) s0 += lo + hi; else s1 += lo + hi;
        }
        msum[0][t] = s0;
        msum[1][t] = s1;
    }
    __syncthreads();

    // ---- coord MLP layer 1: c1 = silu(m_ij @ Wc1 + bc1) -> plain rows ----
    {
        float b1 = bc1[t];
        u64v b12 = pk2(b1, b1);
        #pragma unroll
        for (int q = 0; q < NPG; q++) acc2[q] = b12;
        for (int d = 0; d < HDIM; d += 4) {
            float s0 = Wc1[(d + 0) * HDIM + t];
            float s1 = Wc1[(d + 1) * HDIM + t];
            float s2 = Wc1[(d + 2) * HDIM + t];
            float s3 = Wc1[(d + 3) * HDIM + t];
            u64v w0 = pk2(s0, s0), w1 = pk2(s1, s1), w2 = pk2(s2, s2), w3 = pk2(s3, s3);
            #pragma unroll
            for (int q = 0; q < NPG; q++) {
                const ulonglong2* fp = (const ulonglong2*)&bufAp[q * STR2 + d];
                ulonglong2 q0 = fp[0];
                ulonglong2 q1 = fp[1];
                acc2[q] = fma2(q0.x, w0, acc2[q]);
                acc2[q] = fma2(q0.y, w1, acc2[q]);
                acc2[q] = fma2(q1.x, w2, acc2[q]);
                acc2[q] = fma2(q1.y, w3, acc2[q]);
            }
        }
        // write c1 as 32 plain float rows (row r = g*16+k), stride STR2 floats
        float* bufBf = (float*)bufBp;
        #pragma unroll
        for (int q = 0; q < NPG; q++) {
            int g = q >> 3, p = q & 7;
            float lo, hi;
            upk2(lo, hi, acc2[q]);
            bufBf[(g * KNBR + p) * STR2 + t]     = silu_f(lo);   // edge p
            bufBf[(g * KNBR + p + 8) * STR2 + t] = silu_f(hi);   // edge p+8
        }
    }
    __syncthreads();

    // ---- coord_w = c1 . Wc2 : 32 rows, warp w reduces rows 8w..8w+7 ----
    {
        const float* bufBf = (const float*)bufBp;
        int w = t >> 5, l = t & 31;
        float c0 = Wc2[l], c1v = Wc2[l + 32], c2 = Wc2[l + 64], c3 = Wc2[l + 96];
        #pragma unroll
        for (int rr = 0; rr < 8; rr++) {
            int r = w * 8 + rr;               // r = g*16 + k
            const float* row = &bufBf[r * STR2];
            float p = row[l] * c0 + row[l + 32] * c1v + row[l + 64] * c2 + row[l + 96] * c3;
            p += __shfl_xor_sync(0xffffffffu, p, 16);
            p += __shfl_xor_sync(0xffffffffu, p, 8);
            p += __shfl_xor_sync(0xffffffffu, p, 4);
            p += __shfl_xor_sync(0xffffffffu, p, 2);
            p += __shfl_xor_sync(0xffffffffu, p, 1);
            if (l == 0) cw[r >> 4][r & 15] = p;
        }
    }
    __syncthreads();

    // ---- x_new (threads 0..5: node g component c) ----
    if (t < NODES * 3) {
        int g = t / 3, c = t % 3;
        float s = 0.0f;
        #pragma unroll
        for (int k = 0; k < KNBR; k++) s += xdf[g][k][c] * cw[g][k];
        xout[(long)(n0 + g) * 3 + c] = sxi[g][c] + s * (1.0f / (float)KNBR);
    }

    // ---- node MLP: h_new = silu([h_i, m_i] @ Wn1 + bn1) @ Wn2 + bn2 + h_i ----
    {
        float na0 = bn1[t], na1 = bn1[t];
        #pragma unroll 4
        for (int d = 0; d < HDIM; d += 4) {
            float w0 = Wn1[(d + 0) * HDIM + t];
            float w1 = Wn1[(d + 1) * HDIM + t];
            float w2 = Wn1[(d + 2) * HDIM + t];
            float w3 = Wn1[(d + 3) * HDIM + t];
            float4 f0 = *(const float4*)&shi[0][d];
            float4 f1 = *(const float4*)&shi[1][d];
            na0 = fmaf(f0.x, w0, na0); na1 = fmaf(f1.x, w0, na1);
            na0 = fmaf(f0.y, w1, na0); na1 = fmaf(f1.y, w1, na1);
            na0 = fmaf(f0.z, w2, na0); na1 = fmaf(f1.z, w2, na1);
            na0 = fmaf(f0.w, w3, na0); na1 = fmaf(f1.w, w3, na1);
        }
        const float* Wn1b = Wn1 + HDIM * HDIM;
        #pragma unroll 4
        for (int d = 0; d < HDIM; d += 4) {
            float w0 = Wn1b[(d + 0) * HDIM + t];
            float w1 = Wn1b[(d + 1) * HDIM + t];
            float w2 = Wn1b[(d + 2) * HDIM + t];
            float w3 = Wn1b[(d + 3) * HDIM + t];
            float4 f0 = *(const float4*)&msum[0][d];
            float4 f1 = *(const float4*)&msum[1][d];
            na0 = fmaf(f0.x, w0, na0); na1 = fmaf(f1.x, w0, na1);
            na0 = fmaf(f0.y, w1, na0); na1 = fmaf(f1.y, w1, na1);
            na0 = fmaf(f0.z, w2, na0); na1 = fmaf(f1.z, w2, na1);
            na0 = fmaf(f0.w, w3, na0); na1 = fmaf(f1.w, w3, na1);
        }
        n1b[0][t] = silu_f(na0);
        n1b[1][t] = silu_f(na1);
    }
    __syncthreads();
    {
        float oa0 = bn2[t] + shi[0][t];
        float oa1 = bn2[t] + shi[1][t];
        #pragma unroll 4
        for (int d = 0; d < HDIM; d += 4) {
            float w0 = Wn2[(d + 0) * HDIM + t];
            float w1 = Wn2[(d + 1) * HDIM + t];
            float w2 = Wn2[(d + 2) * HDIM + t];
            float w3 = Wn2[(d + 3) * HDIM + t];
            float4 f0 = *(const float4*)&n1b[0][d];
            float4 f1 = *(const float4*)&n1b[1][d];
            oa0 = fmaf(f0.x, w0, oa0); oa1 = fmaf(f1.x, w0, oa1);
            oa0 = fmaf(f0.y, w1, oa0); oa1 = fmaf(f1.y, w1, oa1);
            oa0 = fmaf(f0.z, w2, oa0); oa1 = fmaf(f1.z, w2, oa1);
            oa0 = fmaf(f0.w, w3, oa0); oa1 = fmaf(f1.w, w3, oa1);
        }
        hout[(long)n0 * HDIM + t]       = oa0;
        hout[(long)(n0 + 1) * HDIM + t] = oa1;
    }
}

extern "C" void kernel_launch(void* const* d_in, const int* in_sizes, int n_in,
                              void* d_out, int out_size) {
    const float* h    = (const float*)d_in[0];
    const float* x    = (const float*)d_in[1];
    const int*   eidx = (const int*)d_in[2];
    const float* We1  = (const float*)d_in[3];
    const float* be1  = (const float*)d_in[4];
    const float* We2  = (const float*)d_in[5];
    const float* be2  = (const float*)d_in[6];
    const float* Wc1  = (const float*)d_in[7];
    const float* bc1  = (const float*)d_in[8];
    const float* Wc2  = (const float*)d_in[9];
    const float* Wn1  = (const float*)d_in[10];
    const float* bn1  = (const float*)d_in[11];
    const float* Wn2  = (const float*)d_in[12];
    const float* bn2  = (const float*)d_in[13];

    float* hout = (float*)d_out;                                  // (B,N,H)
    float* xout = (float*)d_out + (long)BATCH * NPTS * HDIM;      // (B,N,3)

    dim3 grid(BATCH * NPTS / NODES);
    dim3 block(128);
    egnn_layer_kernel<<<grid, block>>>(h, x, eidx,
                                       We1, be1, We2, be2,
                                       Wc1, bc1, Wc2,
                                       Wn1, bn1, Wn2, bn2,
                                       hout, xout);
}

// round 5
// speedup vs baseline: 1.4496x; 1.4150x over previous
#include <cuda_runtime.h>
#include <cuda_bf16.h>

// EGNN layer, B=2, N=16384, K=16, H=128.
// One CTA (128 threads) per TWO nodes.
// Edge-GEMM stages: warps 0-1 own node 0, warps 2-3 own node 1. Each thread
// owns TWO output channels (u, u+64) over its node's 16 edges (8 packed f32x2
// pairs), so each broadcast LDS.128 of packed features feeds 8 FMA2 instead
// of 4 -> LDS wavefronts through the (per-SM, shared) L1TEX pipe are halved.
// fma.rn.f32x2 packs edge pairs (k, k+8); weights are duplicated per channel.
// Node MLP / reductions keep the thread->channel-t mapping over both nodes.

#define HDIM 128
#define BATCH 2
#define NPTS 16384
#define KNBR 16
#define NODES 2
#define NPAIR 8
#define NPG (NODES * NPAIR)   // 16 pair-groups: q = g*8 + p
#define STR2 130              // float2 stride per pair row-block

typedef unsigned long long u64v;

__device__ __forceinline__ float silu_f(float v) {
    return v / (1.0f + __expf(-v));
}

__device__ __forceinline__ u64v pk2(float lo, float hi) {
    u64v r;
    asm("mov.b64 %0, {%1, %2};" : "=l"(r) : "f"(lo), "f"(hi));
    return r;
}
__device__ __forceinline__ void upk2(float& lo, float& hi, u64v v) {
    asm("mov.b64 {%0, %1}, %2;" : "=f"(lo), "=f"(hi) : "l"(v));
}
__device__ __forceinline__ u64v fma2(u64v a, u64v b, u64v c) {
    u64v d;
    asm("fma.rn.f32x2 %0, %1, %2, %3;" : "=l"(d) : "l"(a), "l"(b), "l"(c));
    return d;
}
__device__ __forceinline__ u64v silu2(u64v v) {
    float lo, hi;
    upk2(lo, hi, v);
    return pk2(silu_f(lo), silu_f(hi));
}

__global__ void __launch_bounds__(128)
egnn_layer_kernel(const float* __restrict__ h, const float* __restrict__ x,
                  const int* __restrict__ eidx,
                  const float* __restrict__ We1, const float* __restrict__ be1,
                  const float* __restrict__ We2, const float* __restrict__ be2,
                  const float* __restrict__ Wc1, const float* __restrict__ bc1,
                  const float* __restrict__ Wc2,
                  const float* __restrict__ Wn1, const float* __restrict__ bn1,
                  const float* __restrict__ Wn2, const float* __restrict__ bn2,
                  float* __restrict__ hout, float* __restrict__ xout)
{
    __shared__ __align__(16) float2 bufAp[NPG * STR2]; // packed h_j, later packed m_ij
    __shared__ __align__(16) float2 bufBp[NPG * STR2]; // packed e1, later plain c1 rows
    __shared__ __align__(16) float shi[NODES][HDIM];
    __shared__ __align__(16) float msum[NODES][HDIM];
    __shared__ __align__(16) float n1b[NODES][HDIM];
    __shared__ float sq[NODES][KNBR];
    __shared__ float xdf[NODES][KNBR][3];
    __shared__ float cw[NODES][KNBR];
    __shared__ int   sidx[NODES][KNBR];
    __shared__ float sxi[NODES][3];

    const int t  = threadIdx.x;
    const int g  = t >> 6;         // node half for edge stages
    const int u  = t & 63;         // local channel base
    const int ch0 = u, ch1 = u + 64;
    const int n0 = blockIdx.x * NODES;
    const int b  = n0 / NPTS;

    // ---- stage 0: load node data + indices ----
    shi[0][t] = h[(long)n0 * HDIM + t];
    shi[1][t] = h[(long)(n0 + 1) * HDIM + t];
    if (t < NODES * KNBR) {
        int gg = t >> 4, k = t & 15;
        sidx[gg][k] = eidx[(long)(n0 + gg) * KNBR + k];
    }
    if (t < NODES * 3) {
        int gg = t / 3, c = t % 3;
        sxi[gg][c] = x[(long)(n0 + gg) * 3 + c];
    }
    __syncthreads();

    // per-edge coordinate terms
    if (t < NODES * KNBR) {
        int gg = t >> 4, k = t & 15;
        int j = sidx[gg][k];
        const float* xj = x + ((long)b * NPTS + j) * 3;
        float dx = sxi[gg][0] - xj[0];
        float dy = sxi[gg][1] - xj[1];
        float dz = sxi[gg][2] - xj[2];
        xdf[gg][k][0] = dx; xdf[gg][k][1] = dy; xdf[gg][k][2] = dz;
        sq[gg][k] = dx*dx + dy*dy + dz*dz;
    }

    // gather h_j rows PRE-PACKED: group q=gg*8+p holds {h_j(k=p), h_j(k=p+8)}.
    {
        int w = t >> 5, l = t & 31;
        #pragma unroll
        for (int gg = 0; gg < NODES; gg++) {
            #pragma unroll
            for (int pp = 0; pp < 2; pp++) {
                int p = w + 4 * pp;
                const float4* A  = (const float4*)(h + ((long)b * NPTS + sidx[gg][p]) * HDIM);
                const float4* Bq = (const float4*)(h + ((long)b * NPTS + sidx[gg][p + 8]) * HDIM);
                float4 a = A[l];
                float4 c = Bq[l];
                float2* dst = &bufAp[(gg * NPAIR + p) * STR2 + 4 * l];
                dst[0] = make_float2(a.x, c.x);
                dst[1] = make_float2(a.y, c.y);
                dst[2] = make_float2(a.z, c.z);
                dst[3] = make_float2(a.w, c.w);
            }
        }
    }
    __syncthreads();

    u64v acc2[NPAIR][2];   // [pair][channel 0/1]

    // ---- edge MLP layer 1: e1 = silu([h_i, h_j, sq] @ We1 + be1) ----
    {
        // k-invariant h_i part for node g, channels ch0/ch1
        float a0 = be1[ch0], a1 = be1[ch1];
        #pragma unroll 4
        for (int d = 0; d < HDIM; d += 4) {
            float4 f = *(const float4*)&shi[g][d];
            a0 = fmaf(f.x, We1[(d + 0) * HDIM + ch0], a0);
            a1 = fmaf(f.x, We1[(d + 0) * HDIM + ch1], a1);
            a0 = fmaf(f.y, We1[(d + 1) * HDIM + ch0], a0);
            a1 = fmaf(f.y, We1[(d + 1) * HDIM + ch1], a1);
            a0 = fmaf(f.z, We1[(d + 2) * HDIM + ch0], a0);
            a1 = fmaf(f.z, We1[(d + 2) * HDIM + ch1], a1);
            a0 = fmaf(f.w, We1[(d + 3) * HDIM + ch0], a0);
            a1 = fmaf(f.w, We1[(d + 3) * HDIM + ch1], a1);
        }
        u64v i0 = pk2(a0, a0), i1 = pk2(a1, a1);
        #pragma unroll
        for (int p = 0; p < NPAIR; p++) { acc2[p][0] = i0; acc2[p][1] = i1; }

        const float* W1b = We1 + HDIM * HDIM;  // rows 128..255 (h_j part)
        for (int d = 0; d < HDIM; d += 4) {
            float s00 = W1b[(d + 0) * HDIM + ch0], s01 = W1b[(d + 0) * HDIM + ch1];
            float s10 = W1b[(d + 1) * HDIM + ch0], s11 = W1b[(d + 1) * HDIM + ch1];
            float s20 = W1b[(d + 2) * HDIM + ch0], s21 = W1b[(d + 2) * HDIM + ch1];
            float s30 = W1b[(d + 3) * HDIM + ch0], s31 = W1b[(d + 3) * HDIM + ch1];
            u64v w00 = pk2(s00, s00), w01 = pk2(s01, s01);
            u64v w10 = pk2(s10, s10), w11 = pk2(s11, s11);
            u64v w20 = pk2(s20, s20), w21 = pk2(s21, s21);
            u64v w30 = pk2(s30, s30), w31 = pk2(s31, s31);
            #pragma unroll
            for (int p = 0; p < NPAIR; p++) {
                const ulonglong2* fp = (const ulonglong2*)&bufAp[(g * NPAIR + p) * STR2 + d];
                ulonglong2 q0 = fp[0];   // rows d, d+1
                ulonglong2 q1 = fp[1];   // rows d+2, d+3
                acc2[p][0] = fma2(q0.x, w00, acc2[p][0]);
                acc2[p][1] = fma2(q0.x, w01, acc2[p][1]);
                acc2[p][0] = fma2(q0.y, w10, acc2[p][0]);
                acc2[p][1] = fma2(q0.y, w11, acc2[p][1]);
                acc2[p][0] = fma2(q1.x, w20, acc2[p][0]);
                acc2[p][1] = fma2(q1.x, w21, acc2[p][1]);
                acc2[p][0] = fma2(q1.y, w30, acc2[p][0]);
                acc2[p][1] = fma2(q1.y, w31, acc2[p][1]);
            }
        }
        float wqa = We1[(2 * HDIM) * HDIM + ch0];
        float wqb = We1[(2 * HDIM) * HDIM + ch1];
        u64v wq0 = pk2(wqa, wqa), wq1 = pk2(wqb, wqb);
        #pragma unroll
        for (int p = 0; p < NPAIR; p++) {
            u64v sqp = pk2(sq[g][p], sq[g][p + 8]);
            acc2[p][0] = silu2(fma2(sqp, wq0, acc2[p][0]));
            acc2[p][1] = silu2(fma2(sqp, wq1, acc2[p][1]));
            *(u64v*)&bufBp[(g * NPAIR + p) * STR2 + ch0] = acc2[p][0];
            *(u64v*)&bufBp[(g * NPAIR + p) * STR2 + ch1] = acc2[p][1];
        }
    }
    __syncthreads();

    // ---- edge MLP layer 2: m_ij = silu(e1 @ We2 + be2) ----
    {
        u64v b0 = pk2(be2[ch0], be2[ch0]);
        u64v b1 = pk2(be2[ch1], be2[ch1]);
        #pragma unroll
        for (int p = 0; p < NPAIR; p++) { acc2[p][0] = b0; acc2[p][1] = b1; }
        for (int d = 0; d < HDIM; d += 4) {
            float s00 = We2[(d + 0) * HDIM + ch0], s01 = We2[(d + 0) * HDIM + ch1];
            float s10 = We2[(d + 1) * HDIM + ch0], s11 = We2[(d + 1) * HDIM + ch1];
            float s20 = We2[(d + 2) * HDIM + ch0], s21 = We2[(d + 2) * HDIM + ch1];
            float s30 = We2[(d + 3) * HDIM + ch0], s31 = We2[(d + 3) * HDIM + ch1];
            u64v w00 = pk2(s00, s00), w01 = pk2(s01, s01);
            u64v w10 = pk2(s10, s10), w11 = pk2(s11, s11);
            u64v w20 = pk2(s20, s20), w21 = pk2(s21, s21);
            u64v w30 = pk2(s30, s30), w31 = pk2(s31, s31);
            #pragma unroll
            for (int p = 0; p < NPAIR; p++) {
                const ulonglong2* fp = (const ulonglong2*)&bufBp[(g * NPAIR + p) * STR2 + d];
                ulonglong2 q0 = fp[0];
                ulonglong2 q1 = fp[1];
                acc2[p][0] = fma2(q0.x, w00, acc2[p][0]);
                acc2[p][1] = fma2(q0.x, w01, acc2[p][1]);
                acc2[p][0] = fma2(q0.y, w10, acc2[p][0]);
                acc2[p][1] = fma2(q0.y, w11, acc2[p][1]);
                acc2[p][0] = fma2(q1.x, w20, acc2[p][0]);
                acc2[p][1] = fma2(q1.x, w21, acc2[p][1]);
                acc2[p][0] = fma2(q1.y, w30, acc2[p][0]);
                acc2[p][1] = fma2(q1.y, w31, acc2[p][1]);
            }
        }
        float s0 = 0.0f, s1 = 0.0f;
        #pragma unroll
        for (int p = 0; p < NPAIR; p++) {
            acc2[p][0] = silu2(acc2[p][0]);
            acc2[p][1] = silu2(acc2[p][1]);
            float lo, hi;
            upk2(lo, hi, acc2[p][0]); s0 += lo + hi;
            upk2(lo, hi, acc2[p][1]); s1 += lo + hi;
        }
        msum[g][ch0] = s0;
        msum[g][ch1] = s1;
    }
    __syncthreads();   // bufAp gather reads done (prev stage), safe to overwrite
    {
        #pragma unroll
        for (int p = 0; p < NPAIR; p++) {
            *(u64v*)&bufAp[(g * NPAIR + p) * STR2 + ch0] = acc2[p][0];
            *(u64v*)&bufAp[(g * NPAIR + p) * STR2 + ch1] = acc2[p][1];
        }
    }
    __syncthreads();

    // ---- coord MLP layer 1: c1 = silu(m_ij @ Wc1 + bc1) -> plain rows ----
    {
        u64v b0 = pk2(bc1[ch0], bc1[ch0]);
        u64v b1 = pk2(bc1[ch1], bc1[ch1]);
        #pragma unroll
        for (int p = 0; p < NPAIR; p++) { acc2[p][0] = b0; acc2[p][1] = b1; }
        for (int d = 0; d < HDIM; d += 4) {
            float s00 = Wc1[(d + 0) * HDIM + ch0], s01 = Wc1[(d + 0) * HDIM + ch1];
            float s10 = Wc1[(d + 1) * HDIM + ch0], s11 = Wc1[(d + 1) * HDIM + ch1];
            float s20 = Wc1[(d + 2) * HDIM + ch0], s21 = Wc1[(d + 2) * HDIM + ch1];
            float s30 = Wc1[(d + 3) * HDIM + ch0], s31 = Wc1[(d + 3) * HDIM + ch1];
            u64v w00 = pk2(s00, s00), w01 = pk2(s01, s01);
            u64v w10 = pk2(s10, s10), w11 = pk2(s11, s11);
            u64v w20 = pk2(s20, s20), w21 = pk2(s21, s21);
            u64v w30 = pk2(s30, s30), w31 = pk2(s31, s31);
            #pragma unroll
            for (int p = 0; p < NPAIR; p++) {
                const ulonglong2* fp = (const ulonglong2*)&bufAp[(g * NPAIR + p) * STR2 + d];
                ulonglong2 q0 = fp[0];
                ulonglong2 q1 = fp[1];
                acc2[p][0] = fma2(q0.x, w00, acc2[p][0]);
                acc2[p][1] = fma2(q0.x, w01, acc2[p][1]);
                acc2[p][0] = fma2(q0.y, w10, acc2[p][0]);
                acc2[p][1] = fma2(q0.y, w11, acc2[p][1]);
                acc2[p][0] = fma2(q1.x, w20, acc2[p][0]);
                acc2[p][1] = fma2(q1.x, w21, acc2[p][1]);
                acc2[p][0] = fma2(q1.y, w30, acc2[p][0]);
                acc2[p][1] = fma2(q1.y, w31, acc2[p][1]);
            }
        }
        __syncthreads();   // bufBp (e1) reads done; reuse as plain float c1 rows
        float* bufBf = (float*)bufBp;
        #pragma unroll
        for (int p = 0; p < NPAIR; p++) {
            float lo, hi;
            upk2(lo, hi, acc2[p][0]);
            bufBf[(g * KNBR + p) * STR2 + ch0]     = silu_f(lo);
            bufBf[(g * KNBR + p + 8) * STR2 + ch0] = silu_f(hi);
            upk2(lo, hi, acc2[p][1]);
            bufBf[(g * KNBR + p) * STR2 + ch1]     = silu_f(lo);
            bufBf[(g * KNBR + p + 8) * STR2 + ch1] = silu_f(hi);
        }
    }
    __syncthreads();

    // ---- coord_w = c1 . Wc2 : 32 rows, warp w reduces rows 8w..8w+7 ----
    {
        const float* bufBf = (const float*)bufBp;
        int w = t >> 5, l = t & 31;
        float c0 = Wc2[l], c1v = Wc2[l + 32], c2 = Wc2[l + 64], c3 = Wc2[l + 96];
        #pragma unroll
        for (int rr = 0; rr < 8; rr++) {
            int r = w * 8 + rr;               // r = gg*16 + k
            const float* row = &bufBf[r * STR2];
            float p = row[l] * c0 + row[l + 32] * c1v + row[l + 64] * c2 + row[l + 96] * c3;
            p += __shfl_xor_sync(0xffffffffu, p, 16);
            p += __shfl_xor_sync(0xffffffffu, p, 8);
            p += __shfl_xor_sync(0xffffffffu, p, 4);
            p += __shfl_xor_sync(0xffffffffu, p, 2);
            p += __shfl_xor_sync(0xffffffffu, p, 1);
            if (l == 0) cw[r >> 4][r & 15] = p;
        }
    }
    __syncthreads();

    // ---- x_new (threads 0..5: node gg component c) ----
    if (t < NODES * 3) {
        int gg = t / 3, c = t % 3;
        float s = 0.0f;
        #pragma unroll
        for (int k = 0; k < KNBR; k++) s += xdf[gg][k][c] * cw[gg][k];
        xout[(long)(n0 + gg) * 3 + c] = sxi[gg][c] + s * (1.0f / (float)KNBR);
    }

    // ---- node MLP: h_new = silu([h_i, m_i] @ Wn1 + bn1) @ Wn2 + bn2 + h_i ----
    {
        float na0 = bn1[t], na1 = bn1[t];
        #pragma unroll 4
        for (int d = 0; d < HDIM; d += 4) {
            float w0 = Wn1[(d + 0) * HDIM + t];
            float w1 = Wn1[(d + 1) * HDIM + t];
            float w2 = Wn1[(d + 2) * HDIM + t];
            float w3 = Wn1[(d + 3) * HDIM + t];
            float4 f0 = *(const float4*)&shi[0][d];
            float4 f1 = *(const float4*)&shi[1][d];
            na0 = fmaf(f0.x, w0, na0); na1 = fmaf(f1.x, w0, na1);
            na0 = fmaf(f0.y, w1, na0); na1 = fmaf(f1.y, w1, na1);
            na0 = fmaf(f0.z, w2, na0); na1 = fmaf(f1.z, w2, na1);
            na0 = fmaf(f0.w, w3, na0); na1 = fmaf(f1.w, w3, na1);
        }
        const float* Wn1b = Wn1 + HDIM * HDIM;
        #pragma unroll 4
        for (int d = 0; d < HDIM; d += 4) {
            float w0 = Wn1b[(d + 0) * HDIM + t];
            float w1 = Wn1b[(d + 1) * HDIM + t];
            float w2 = Wn1b[(d + 2) * HDIM + t];
            float w3 = Wn1b[(d + 3) * HDIM + t];
            float4 f0 = *(const float4*)&msum[0][d];
            float4 f1 = *(const float4*)&msum[1][d];
            na0 = fmaf(f0.x, w0, na0); na1 = fmaf(f1.x, w0, na1);
            na0 = fmaf(f0.y, w1, na0); na1 = fmaf(f1.y, w1, na1);
            na0 = fmaf(f0.z, w2, na0); na1 = fmaf(f1.z, w2, na1);
            na0 = fmaf(f0.w, w3, na0); na1 = fmaf(f1.w, w3, na1);
        }
        n1b[0][t] = silu_f(na0);
        n1b[1][t] = silu_f(na1);
    }
    __syncthreads();
    {
        float oa0 = bn2[t] + shi[0][t];
        float oa1 = bn2[t] + shi[1][t];
        #pragma unroll 4
        for (int d = 0; d < HDIM; d += 4) {
            float w0 = Wn2[(d + 0) * HDIM + t];
            float w1 = Wn2[(d + 1) * HDIM + t];
            float w2 = Wn2[(d + 2) * HDIM + t];
            float w3 = Wn2[(d + 3) * HDIM + t];
            float4 f0 = *(const float4*)&n1b[0][d];
            float4 f1 = *(const float4*)&n1b[1][d];
            oa0 = fmaf(f0.x, w0, oa0); oa1 = fmaf(f1.x, w0, oa1);
            oa0 = fmaf(f0.y, w1, oa0); oa1 = fmaf(f1.y, w1, oa1);
            oa0 = fmaf(f0.z, w2, oa0); oa1 = fmaf(f1.z, w2, oa1);
            oa0 = fmaf(f0.w, w3, oa0); oa1 = fmaf(f1.w, w3, oa1);
        }
        hout[(long)n0 * HDIM + t]       = oa0;
        hout[(long)(n0 + 1) * HDIM + t] = oa1;
    }
}

extern "C" void kernel_launch(void* const* d_in, const int* in_sizes, int n_in,
                              void* d_out, int out_size) {
    const float* h    = (const float*)d_in[0];
    const float* x    = (const float*)d_in[1];
    const int*   eidx = (const int*)d_in[2];
    const float* We1  = (const float*)d_in[3];
    const float* be1  = (const float*)d_in[4];
    const float* We2  = (const float*)d_in[5];
    const float* be2  = (const float*)d_in[6];
    const float* Wc1  = (const float*)d_in[7];
    const float* bc1  = (const float*)d_in[8];
    const float* Wc2  = (const float*)d_in[9];
    const float* Wn1  = (const float*)d_in[10];
    const float* bn1  = (const float*)d_in[11];
    const float* Wn2  = (const float*)d_in[12];
    const float* bn2  = (const float*)d_in[13];

    float* hout = (float*)d_out;                                  // (B,N,H)
    float* xout = (float*)d_out + (long)BATCH * NPTS * HDIM;      // (B,N,3)

    dim3 grid(BATCH * NPTS / NODES);
    dim3 block(128);
    egnn_layer_kernel<<<grid, block>>>(h, x, eidx,
                                       We1, be1, We2, be2,
                                       Wc1, bc1, Wc2,
                                       Wn1, bn1, Wn2, bn2,
                                       hout, xout);
}